// round 11
// baseline (speedup 1.0000x reference)
#include <cuda_runtime.h>
#include <cuda_fp16.h>

// ---------------------------------------------------------------------------
// f16-accumulate MMA + movmatrix wrappers (sm_75+/sm_80, fine on compute_103)
// ---------------------------------------------------------------------------
__device__ __forceinline__ void mmaf16_16816(unsigned* d, const unsigned* a,
                                             unsigned b0, unsigned b1,
                                             unsigned c0, unsigned c1) {
    asm volatile(
        "mma.sync.aligned.m16n8k16.row.col.f16.f16.f16.f16 "
        "{%0,%1}, {%2,%3,%4,%5}, {%6,%7}, {%8,%9};"
        : "=r"(d[0]), "=r"(d[1])
        : "r"(a[0]), "r"(a[1]), "r"(a[2]), "r"(a[3]),
          "r"(b0), "r"(b1), "r"(c0), "r"(c1));
}
__device__ __forceinline__ void mmaf16_1688(unsigned* d, const unsigned* a,
                                            unsigned b0,
                                            unsigned c0, unsigned c1) {
    asm volatile(
        "mma.sync.aligned.m16n8k8.row.col.f16.f16.f16.f16 "
        "{%0,%1}, {%2,%3}, {%4}, {%5,%6};"
        : "=r"(d[0]), "=r"(d[1])
        : "r"(a[0]), "r"(a[1]), "r"(b0), "r"(c0), "r"(c1));
}
__device__ __forceinline__ unsigned movmt(unsigned a) {
    unsigned d;
    asm("movmatrix.sync.aligned.m8n8.trans.b16 %0, %1;" : "=r"(d) : "r"(a));
    return d;
}
__device__ __forceinline__ __half2 tanh2(__half2 x) {
    unsigned xi = *reinterpret_cast<unsigned*>(&x), yi;
    asm("tanh.approx.f16x2 %0, %1;" : "=r"(yi) : "r"(xi));
    return *reinterpret_cast<__half2*>(&yi);
}
// sigmoid with the 0.5 pre-folded into the weights: sig(2y) = 0.5*tanh(y)+0.5
__device__ __forceinline__ __half2 sig2h(__half2 y) {
    const __half2 h05 = __float2half2_rn(0.5f);
    return __hfma2(tanh2(y), h05, h05);
}
__device__ __forceinline__ unsigned pack2(float lo, float hi) {
    __half2 h = __floats2half2_rn(lo, hi);
    return *reinterpret_cast<unsigned*>(&h);
}
__device__ __forceinline__ __half2 u2h(unsigned u) {
    return *reinterpret_cast<__half2*>(&u);
}

// ---------------------------------------------------------------------------
// Gate-split fused LSTM, TWO independent 8-row chains per warp pair.
// CTA = 2 warps, 16 batch rows (chain A: rows 0-7, chain B: rows 8-15).
// Warp p owns units [16p,16p+16), all 4 gates, for BOTH chains; weights
// (40 regs) shared. Chain B's MMAs fill chain A's MMA/MUFU latency inside
// the same warp. One barrier + one STS.128/LDS.128 exchange per 2 chains.
// ---------------------------------------------------------------------------
__global__ void __launch_bounds__(64, 7) lstm_fused(
    const float* __restrict__ x,
    const int* __restrict__ mat_idx, const int* __restrict__ freq_idx,
    const float* __restrict__ W_ih, const float* __restrict__ W_hh,
    const float* __restrict__ b_ih, const float* __restrict__ b_hh,
    const float* __restrict__ mat_emb, const float* __restrict__ freq_emb,
    const float* __restrict__ fc_w, const float* __restrict__ fc_b,
    float* __restrict__ out, int T)
{
    __shared__ ulonglong2 sx[2][2][32];   // [buf][warp][lane]: .x=A, .y=B
    __shared__ float sred[2][2][4][2];    // [warp][chain][q][lo/hi]
    __shared__ unsigned s_xh[32][16][2];  // [step][slot=gid*2+q][chain]

    const int tid  = threadIdx.x;
    const int wid  = tid >> 5, lane = tid & 31;
    const int q    = lane & 3;            // batch col-pair selector
    const int gid  = lane >> 2;           // row-in-tile

    const long long rowbase = (long long)blockIdx.x * 16;

    // ---- stationary A fragments; 0.5 folded into sigmoid gates (i,f,o) ----
    auto wval = [&](int n, int k) -> float {
        float v;
        if (k < 32)       v = W_hh[n * 32 + k];
        else if (k < 35)  v = W_ih[n * 3 + (k - 32)];
        else if (k == 35) v = b_ih[n] + b_hh[n];
        else              v = 0.f;
        if ((n >> 5) != 2) v *= 0.5f;      // gates i,f,o scaled; g untouched
        return v;
    };
    unsigned af[4][2][4];   // gate, k16-chunk, frag
    unsigned af2[4][2];     // k8 chunk (x + bias)
#pragma unroll
    for (int g = 0; g < 4; ++g) {
        int n0 = g * 32 + 16 * wid + gid, n1 = n0 + 8;
#pragma unroll
        for (int kc = 0; kc < 2; ++kc) {
            int k0 = 16 * kc + 2 * q;
            af[g][kc][0] = pack2(wval(n0, k0),     wval(n0, k0 + 1));
            af[g][kc][1] = pack2(wval(n1, k0),     wval(n1, k0 + 1));
            af[g][kc][2] = pack2(wval(n0, k0 + 8), wval(n0, k0 + 9));
            af[g][kc][3] = pack2(wval(n1, k0 + 8), wval(n1, k0 + 9));
        }
        int k2 = 32 + 2 * q;
        af2[g][0] = pack2(wval(n0, k2), wval(n0, k2 + 1));
        af2[g][1] = pack2(wval(n1, k2), wval(n1, k2 + 1));
    }

    // ---- x staging: thread (xrow=tid>>2 of 16 rows, xseg=tid&3) covers
    //      steps [8*xseg, 8*xseg+8) of its row per 32-step chunk ----
    const int xrow = tid >> 2, xseg = tid & 3;
    const int xch = xrow >> 3, xr8 = xrow & 7;
    const float4* xsrc =
        reinterpret_cast<const float4*>(x + (size_t)(rowbase + xrow) * T * 3)
        + xseg * 6;                        // 24 floats per chunk-slice

    // ---- loop-carried state per chain ----
    unsigned b00[2] = {0,0}, b01[2] = {0,0}, b10[2] = {0,0}, b11[2] = {0,0};
    __half2 cst[2][2];
#pragma unroll
    for (int c = 0; c < 2; ++c) {
        cst[c][0] = __float2half2_rn(0.f);
        cst[c][1] = __float2half2_rn(0.f);
    }
    unsigned hs[2][2];
    hs[0][0] = hs[0][1] = hs[1][0] = hs[1][1] = 0u;

    const bool xlane = (q < 2);
    // reader base: &s_xh[0][gid*2+q][0]; step stride = 32 words
    const unsigned* xrd = &s_xh[0][gid * 2 + q][0];

    for (int tc = 0; tc < T; tc += 32) {
        // ---- stage chunk: 6x LDG.128 per thread, pre-pack to half2 ----
        {
            const float4* src = xsrc + (tc >> 5) * 24;
            float f[24];
#pragma unroll
            for (int j = 0; j < 6; ++j) {
                float4 v = src[j];
                f[4*j] = v.x; f[4*j+1] = v.y; f[4*j+2] = v.z; f[4*j+3] = v.w;
            }
#pragma unroll
            for (int k = 0; k < 8; ++k) {
                int st = 8 * xseg + k;
                s_xh[st][xr8 * 2 + 0][xch] = pack2(f[3*k],     f[3*k + 1]);
                s_xh[st][xr8 * 2 + 1][xch] = pack2(f[3*k + 2], 1.0f);
            }
        }
        __syncthreads();

#pragma unroll 2
        for (int tl = 0; tl < 32; ++tl) {
            const int buf = tl & 1;

            // x fragments for both chains: one LDS.64 (chains adjacent)
            unsigned b2[2] = {0u, 0u};
            if (xlane) {
                const uint2 v = *reinterpret_cast<const uint2*>(xrd + tl * 32);
                b2[0] = v.x; b2[1] = v.y;
            }

            // ---- chain A then chain B MMAs (independent, interleavable) ----
            unsigned acc[2][4][2];
#pragma unroll
            for (int c = 0; c < 2; ++c) {
#pragma unroll
                for (int g = 0; g < 4; ++g)
                    mmaf16_1688(acc[c][g], af2[g], b2[c], 0u, 0u);
#pragma unroll
                for (int g = 0; g < 4; ++g)
                    mmaf16_16816(acc[c][g], af[g][0], b00[c], b01[c],
                                 acc[c][g][0], acc[c][g][1]);
#pragma unroll
                for (int g = 0; g < 4; ++g)
                    mmaf16_16816(acc[c][g], af[g][1], b10[c], b11[c],
                                 acc[c][g][0], acc[c][g][1]);
            }

            // ---- epilogues (A's MUFU overlaps B's MMA latency) ----
            ulonglong2 pkt;
#pragma unroll
            for (int c = 0; c < 2; ++c) {
#pragma unroll
                for (int s = 0; s < 2; ++s) {
                    __half2 si = sig2h(u2h(acc[c][0][s]));
                    __half2 sf = sig2h(u2h(acc[c][1][s]));
                    __half2 tg = tanh2(u2h(acc[c][2][s]));
                    __half2 so = sig2h(u2h(acc[c][3][s]));
                    __half2 cc = __hfma2(sf, cst[c][s], __hmul2(si, tg));
                    cst[c][s] = cc;
                    __half2 hv = __hmul2(so, tanh2(cc));
                    hs[c][s] = *reinterpret_cast<unsigned*>(&hv);
                }
            }
            unsigned fA0 = movmt(hs[0][0]), fA1 = movmt(hs[0][1]);
            unsigned fB0 = movmt(hs[1][0]), fB1 = movmt(hs[1][1]);
            pkt.x = (unsigned long long)fA0 | ((unsigned long long)fA1 << 32);
            pkt.y = (unsigned long long)fB0 | ((unsigned long long)fB1 << 32);
            sx[buf][wid][lane] = pkt;
            __syncthreads();
            const ulonglong2 w = sx[buf][wid ^ 1][lane];
            if (wid == 0) {
                b00[0] = fA0;            b01[0] = fA1;
                b10[0] = (unsigned)w.x;  b11[0] = (unsigned)(w.x >> 32);
                b00[1] = fB0;            b01[1] = fB1;
                b10[1] = (unsigned)w.y;  b11[1] = (unsigned)(w.y >> 32);
            } else {
                b00[0] = (unsigned)w.x;  b01[0] = (unsigned)(w.x >> 32);
                b10[0] = fA0;            b11[0] = fA1;
                b00[1] = (unsigned)w.y;  b01[1] = (unsigned)(w.y >> 32);
                b10[1] = fB0;            b11[1] = fB1;
            }
        }
    }

    // ---- fc head: per-chain partials over this warp's 16 units ----
#pragma unroll
    for (int c = 0; c < 2; ++c) {
        float p_lo = 0.f, p_hi = 0.f;     // rows rowbase+8c+2q, +2q+1
#pragma unroll
        for (int s = 0; s < 2; ++s) {
            __half2 hv = u2h(hs[c][s]);
            float w = fc_w[16 * wid + 8 * s + gid];
            p_lo = fmaf(__low2float(hv),  w, p_lo);
            p_hi = fmaf(__high2float(hv), w, p_hi);
        }
#pragma unroll
        for (int off = 4; off < 32; off <<= 1) {
            p_lo += __shfl_xor_sync(0xFFFFFFFFu, p_lo, off);
            p_hi += __shfl_xor_sync(0xFFFFFFFFu, p_hi, off);
        }
        if (lane < 4) { sred[wid][c][q][0] = p_lo; sred[wid][c][q][1] = p_hi; }
    }
    __syncthreads();
    if (tid < 8) {
        const int c = tid >> 2, qq = tid & 3;
        float base = fc_b[0];
#pragma unroll
        for (int k = 0; k < 2; ++k) {
            long long r = rowbase + 8 * c + 2 * qq + k;
            float s = sred[0][c][qq][k] + sred[1][c][qq][k] + base;
            int mi = mat_idx[r], fi = freq_idx[r];
#pragma unroll
            for (int e = 0; e < 4; ++e) s += mat_emb[mi * 4 + e] * fc_w[32 + e];
#pragma unroll
            for (int e = 0; e < 2; ++e) s += freq_emb[fi * 2 + e] * fc_w[36 + e];
            out[r] = s;
        }
    }
}

extern "C" void kernel_launch(void* const* d_in, const int* in_sizes, int n_in,
                              void* d_out, int out_size) {
    const float* x        = (const float*)d_in[0];
    const int*   mat_idx  = (const int*)  d_in[1];
    const int*   freq_idx = (const int*)  d_in[2];
    const float* W_ih     = (const float*)d_in[3];
    const float* W_hh     = (const float*)d_in[4];
    const float* b_ih     = (const float*)d_in[5];
    const float* b_hh     = (const float*)d_in[6];
    const float* mat_emb  = (const float*)d_in[7];
    const float* freq_emb = (const float*)d_in[8];
    const float* fc_w     = (const float*)d_in[9];
    const float* fc_b     = (const float*)d_in[10];

    int B = in_sizes[1];                  // mat_idx has B elements
    int T = in_sizes[0] / (B * 3);        // x has B*T*3 elements
    int grid = B / 16;                    // 16 rows per 2-warp CTA (2 chains)

    lstm_fused<<<grid, 64>>>(x, mat_idx, freq_idx, W_ih, W_hh, b_ih, b_hh,
                             mat_emb, freq_emb, fc_w, fc_b,
                             (float*)d_out, T);
}

// round 12
// speedup vs baseline: 1.1727x; 1.1727x over previous
#include <cuda_runtime.h>
#include <cuda_fp16.h>

// ---------------------------------------------------------------------------
// f16-accumulate MMA + movmatrix wrappers (sm_75+/sm_80, fine on compute_103)
// ---------------------------------------------------------------------------
__device__ __forceinline__ void mmaf16_16816(unsigned* d, const unsigned* a,
                                             unsigned b0, unsigned b1,
                                             unsigned c0, unsigned c1) {
    asm volatile(
        "mma.sync.aligned.m16n8k16.row.col.f16.f16.f16.f16 "
        "{%0,%1}, {%2,%3,%4,%5}, {%6,%7}, {%8,%9};"
        : "=r"(d[0]), "=r"(d[1])
        : "r"(a[0]), "r"(a[1]), "r"(a[2]), "r"(a[3]),
          "r"(b0), "r"(b1), "r"(c0), "r"(c1));
}
__device__ __forceinline__ void mmaf16_1688(unsigned* d, const unsigned* a,
                                            unsigned b0,
                                            unsigned c0, unsigned c1) {
    asm volatile(
        "mma.sync.aligned.m16n8k8.row.col.f16.f16.f16.f16 "
        "{%0,%1}, {%2,%3}, {%4}, {%5,%6};"
        : "=r"(d[0]), "=r"(d[1])
        : "r"(a[0]), "r"(a[1]), "r"(b0), "r"(c0), "r"(c1));
}
__device__ __forceinline__ unsigned movmt(unsigned a) {
    unsigned d;
    asm("movmatrix.sync.aligned.m8n8.trans.b16 %0, %1;" : "=r"(d) : "r"(a));
    return d;
}
__device__ __forceinline__ __half2 tanh2(__half2 x) {
    unsigned xi = *reinterpret_cast<unsigned*>(&x), yi;
    asm("tanh.approx.f16x2 %0, %1;" : "=r"(yi) : "r"(xi));
    return *reinterpret_cast<__half2*>(&yi);
}
// sigmoid with the 0.5 pre-folded into the weights: sig(2y) = 0.5*tanh(y)+0.5
__device__ __forceinline__ __half2 sig2h(__half2 y) {
    const __half2 h05 = __float2half2_rn(0.5f);
    return __hfma2(tanh2(y), h05, h05);
}
__device__ __forceinline__ unsigned pack2(float lo, float hi) {
    __half2 h = __floats2half2_rn(lo, hi);
    return *reinterpret_cast<unsigned*>(&h);
}
__device__ __forceinline__ __half2 u2h(unsigned u) {
    return *reinterpret_cast<__half2*>(&u);
}

// ---------------------------------------------------------------------------
// Gate-split fused LSTM: 2-warp CTA owns 8 batch rows; warp p owns units
// [16p,16p+16), all 4 gates. R12:
//  - per-warp weight chunk permutation: chunk0 = THIS warp's 16 k-cols,
//    chunk1 = partner's -> branchless exchange (no wid-conditional swap);
//  - own-half MMAs + t+1 x-projection issue BEFORE the barrier (on the
//    movmatrix outputs), so the post-barrier chain is only
//    LDS.64 -> 4 parallel partner MMAs -> epilogue.
// ---------------------------------------------------------------------------
__global__ void __launch_bounds__(64, 13) lstm_fused(
    const float* __restrict__ x,
    const int* __restrict__ mat_idx, const int* __restrict__ freq_idx,
    const float* __restrict__ W_ih, const float* __restrict__ W_hh,
    const float* __restrict__ b_ih, const float* __restrict__ b_hh,
    const float* __restrict__ mat_emb, const float* __restrict__ freq_emb,
    const float* __restrict__ fc_w, const float* __restrict__ fc_b,
    float* __restrict__ out, int T)
{
    __shared__ unsigned long long sx[2][2][32];  // [buf][warp][lane] h-frags
    __shared__ float sred[2][4][2];              // fc partials
    __shared__ unsigned s_xh[32][16];            // [step][row*2+q] packed x

    const int tid  = threadIdx.x;
    const int wid  = tid >> 5, lane = tid & 31;
    const int q    = lane & 3;            // batch col-pair selector
    const int gid  = lane >> 2;           // row-in-tile

    const long long rowbase = (long long)blockIdx.x * 8;

    // ---- stationary A fragments; 0.5 folded into sigmoid gates (i,f,o);
    //      chunk0 = own k-cols [16*wid,16*wid+16), chunk1 = partner's ----
    auto wval = [&](int n, int k) -> float {
        float v;
        if (k < 32)       v = W_hh[n * 32 + k];
        else if (k < 35)  v = W_ih[n * 3 + (k - 32)];
        else if (k == 35) v = b_ih[n] + b_hh[n];
        else              v = 0.f;
        if ((n >> 5) != 2) v *= 0.5f;      // gates i,f,o scaled; g untouched
        return v;
    };
    unsigned af[4][2][4];   // gate, chunk(own/partner), frag
    unsigned af2[4][2];     // k8 chunk (x + bias)
#pragma unroll
    for (int g = 0; g < 4; ++g) {
        int n0 = g * 32 + 16 * wid + gid, n1 = n0 + 8;
#pragma unroll
        for (int kc = 0; kc < 2; ++kc) {
            int k0 = 16 * ((kc == 0) ? wid : (1 - wid)) + 2 * q;
            af[g][kc][0] = pack2(wval(n0, k0),     wval(n0, k0 + 1));
            af[g][kc][1] = pack2(wval(n1, k0),     wval(n1, k0 + 1));
            af[g][kc][2] = pack2(wval(n0, k0 + 8), wval(n0, k0 + 9));
            af[g][kc][3] = pack2(wval(n1, k0 + 8), wval(n1, k0 + 9));
        }
        int k2 = 32 + 2 * q;
        af2[g][0] = pack2(wval(n0, k2), wval(n0, k2 + 1));
        af2[g][1] = pack2(wval(n1, k2), wval(n1, k2 + 1));
    }

    // ---- x staging setup: thread (xr=tid>>3, xseg=tid&7) handles 4 steps ----
    const int xr = tid >> 3, xseg = tid & 7;
    const float4* xsrc =
        reinterpret_cast<const float4*>(x + (size_t)(rowbase + xr) * T * 3)
        + xseg * 3;                        // 12 floats = steps 4*xseg..+4

    // ---- loop-carried state ----
    __half2 cst[2];
    cst[0] = __float2half2_rn(0.f);
    cst[1] = __float2half2_rn(0.f);
    unsigned hs[2];
    hs[0] = hs[1] = 0u;
    unsigned acc[4][2];                    // holds own-half(t)+xproj(t) at top
#pragma unroll
    for (int g = 0; g < 4; ++g) { acc[g][0] = 0u; acc[g][1] = 0u; }

    // first partner read is sx[1] (tl=0 reads buf (0+1)&1) -> zero it
    sx[1][wid][lane] = 0ull;

    const bool xlane = (q < 2);
    const unsigned* xrd = &s_xh[0][gid * 2 + q];  // step stride = 16 words

    for (int tc = 0; tc < T; tc += 32) {
        // ---- stage chunk: 3x LDG.128, pre-pack to half2, STS ----
        {
            const float4* src = xsrc + (tc >> 5) * 24;   // 96 floats/chunk/row
            float4 v0 = src[0], v1 = src[1], v2 = src[2];
            float f[12] = {v0.x, v0.y, v0.z, v0.w, v1.x, v1.y, v1.z, v1.w,
                           v2.x, v2.y, v2.z, v2.w};
#pragma unroll
            for (int k = 0; k < 4; ++k) {
                s_xh[xseg * 4 + k][xr * 2 + 0] = pack2(f[3 * k], f[3 * k + 1]);
                s_xh[xseg * 4 + k][xr * 2 + 1] = pack2(f[3 * k + 2], 1.0f);
            }
        }
        __syncthreads();

        // deferred x-projection for step tc (acc already has own-half(tc))
        {
            unsigned b2 = xlane ? xrd[0] : 0u;
#pragma unroll
            for (int g = 0; g < 4; ++g)
                mmaf16_1688(acc[g], af2[g], b2, acc[g][0], acc[g][1]);
        }

#pragma unroll 4
        for (int tl = 0; tl < 32; ++tl) {
            // ---- read partner fragments (published last iteration) ----
            const unsigned long long w = sx[(tl + 1) & 1][wid ^ 1][lane];
            const unsigned p0 = (unsigned)w, p1 = (unsigned)(w >> 32);

            // ---- 4 parallel partner-half MMAs complete the gates ----
#pragma unroll
            for (int g = 0; g < 4; ++g)
                mmaf16_16816(acc[g], af[g][1], p0, p1, acc[g][0], acc[g][1]);

            // ---- LSTM update (i,f,o pre-scaled by 0.5 in weights) ----
#pragma unroll
            for (int s = 0; s < 2; ++s) {
                __half2 si = sig2h(u2h(acc[0][s]));
                __half2 sf = sig2h(u2h(acc[1][s]));
                __half2 tg = tanh2(u2h(acc[2][s]));
                __half2 so = sig2h(u2h(acc[3][s]));
                __half2 cc = __hfma2(sf, cst[s], __hmul2(si, tg));
                cst[s] = cc;
                __half2 hv = __hmul2(so, tanh2(cc));
                hs[s] = *reinterpret_cast<unsigned*>(&hv);
            }

            // ---- own fragments; own-half MMA for t+1 pre-barrier ----
            unsigned f0 = movmt(hs[0]);    // own k-rows [16*wid, 16*wid+8)
            unsigned f1 = movmt(hs[1]);    // own k-rows [16*wid+8, 16*wid+16)
#pragma unroll
            for (int g = 0; g < 4; ++g)
                mmaf16_16816(acc[g], af[g][0], f0, f1, 0u, 0u);

            // barrier shadow: x-projection for t+1 (same chunk only)
            if (tl < 31) {
                unsigned b2n = xlane ? xrd[(tl + 1) * 16] : 0u;
#pragma unroll
                for (int g = 0; g < 4; ++g)
                    mmaf16_1688(acc[g], af2[g], b2n, acc[g][0], acc[g][1]);
            }

            // ---- publish own fragments for the partner ----
            sx[tl & 1][wid][lane] =
                (unsigned long long)f0 | ((unsigned long long)f1 << 32);
            __syncthreads();
        }
    }

    // ---- fc head: partial over this warp's 16 units, then pair-reduce ----
    float p_lo = 0.f, p_hi = 0.f;          // batch rows rowbase+2q, +2q+1
#pragma unroll
    for (int s = 0; s < 2; ++s) {
        __half2 hv = u2h(hs[s]);
        float w = fc_w[16 * wid + 8 * s + gid];
        p_lo = fmaf(__low2float(hv),  w, p_lo);
        p_hi = fmaf(__high2float(hv), w, p_hi);
    }
#pragma unroll
    for (int off = 4; off < 32; off <<= 1) {
        p_lo += __shfl_xor_sync(0xFFFFFFFFu, p_lo, off);
        p_hi += __shfl_xor_sync(0xFFFFFFFFu, p_hi, off);
    }
    if (lane < 4) { sred[wid][q][0] = p_lo; sred[wid][q][1] = p_hi; }
    __syncthreads();
    if (tid < 4) {
        float base = fc_b[0];
#pragma unroll
        for (int k = 0; k < 2; ++k) {
            long long r = rowbase + 2 * tid + k;
            float s = sred[0][tid][k] + sred[1][tid][k] + base;
            int mi = mat_idx[r], fi = freq_idx[r];
#pragma unroll
            for (int e = 0; e < 4; ++e) s += mat_emb[mi * 4 + e] * fc_w[32 + e];
#pragma unroll
            for (int e = 0; e < 2; ++e) s += freq_emb[fi * 2 + e] * fc_w[36 + e];
            out[r] = s;
        }
    }
}

extern "C" void kernel_launch(void* const* d_in, const int* in_sizes, int n_in,
                              void* d_out, int out_size) {
    const float* x        = (const float*)d_in[0];
    const int*   mat_idx  = (const int*)  d_in[1];
    const int*   freq_idx = (const int*)  d_in[2];
    const float* W_ih     = (const float*)d_in[3];
    const float* W_hh     = (const float*)d_in[4];
    const float* b_ih     = (const float*)d_in[5];
    const float* b_hh     = (const float*)d_in[6];
    const float* mat_emb  = (const float*)d_in[7];
    const float* freq_emb = (const float*)d_in[8];
    const float* fc_w     = (const float*)d_in[9];
    const float* fc_b     = (const float*)d_in[10];

    int B = in_sizes[1];                  // mat_idx has B elements
    int T = in_sizes[0] / (B * 3);        // x has B*T*3 elements
    int grid = B / 8;                     // 8 rows per 2-warp CTA

    lstm_fused<<<grid, 64>>>(x, mat_idx, freq_idx, W_ih, W_hh, b_ih, b_hh,
                             mat_emb, freq_emb, fc_w, fc_b,
                             (float*)d_out, T);
}

// round 13
// speedup vs baseline: 1.2500x; 1.0659x over previous
#include <cuda_runtime.h>
#include <cuda_fp16.h>
#include <math.h>

// ---------------------------------------------------------------------------
// f16-accumulate MMA + movmatrix wrappers (sm_75+/sm_80, fine on compute_103)
// ---------------------------------------------------------------------------
__device__ __forceinline__ void mmaf16_16816(unsigned* d, const unsigned* a,
                                             unsigned b0, unsigned b1,
                                             unsigned c0, unsigned c1) {
    asm volatile(
        "mma.sync.aligned.m16n8k16.row.col.f16.f16.f16.f16 "
        "{%0,%1}, {%2,%3,%4,%5}, {%6,%7}, {%8,%9};"
        : "=r"(d[0]), "=r"(d[1])
        : "r"(a[0]), "r"(a[1]), "r"(a[2]), "r"(a[3]),
          "r"(b0), "r"(b1), "r"(c0), "r"(c1));
}
__device__ __forceinline__ void mmaf16_1688(unsigned* d, const unsigned* a,
                                            unsigned b0,
                                            unsigned c0, unsigned c1) {
    asm volatile(
        "mma.sync.aligned.m16n8k8.row.col.f16.f16.f16.f16 "
        "{%0,%1}, {%2,%3}, {%4}, {%5,%6};"
        : "=r"(d[0]), "=r"(d[1])
        : "r"(a[0]), "r"(a[1]), "r"(b0), "r"(c0), "r"(c1));
}
__device__ __forceinline__ unsigned movmt(unsigned a) {
    unsigned d;
    asm("movmatrix.sync.aligned.m8n8.trans.b16 %0, %1;" : "=r"(d) : "r"(a));
    return d;
}
__device__ __forceinline__ __half2 tanh2(__half2 x) {
    unsigned xi = *reinterpret_cast<unsigned*>(&x), yi;
    asm("tanh.approx.f16x2 %0, %1;" : "=r"(yi) : "r"(xi));
    return *reinterpret_cast<__half2*>(&yi);
}
// sigmoid with the 0.5 pre-folded into the weights: sig(2y) = 0.5*tanh(y)+0.5
__device__ __forceinline__ __half2 sig2h(__half2 y) {
    const __half2 h05 = __float2half2_rn(0.5f);
    return __hfma2(tanh2(y), h05, h05);
}
__device__ __forceinline__ unsigned pack2(float lo, float hi) {
    __half2 h = __floats2half2_rn(lo, hi);
    return *reinterpret_cast<unsigned*>(&h);
}
__device__ __forceinline__ __half2 u2h(unsigned u) {
    return *reinterpret_cast<__half2*>(&u);
}

// ---- LUT sigmoid (no MUFU): sigma = 0.5 + sign(y) * lut[|y| bit-bucket] ----
// lut[j] = 0.5*tanh(value of f16 bits (j<<2)|2), j in [0, 4416).
static constexpr int LUT_N = 4420;
__device__ __forceinline__ __half2 sig_lut(unsigned yu,
                                           const unsigned short* lut) {
    unsigned au = yu & 0x7FFF7FFFu;                  // |y| per half
    __half2 a = *reinterpret_cast<__half2*>(&au);
    a = __hmin2(a, __float2half2_rn(4.99f));         // clamp below 5.0
    unsigned ac = *reinterpret_cast<unsigned*>(&a);
    unsigned i0 = (ac >> 2) & 0x3FFFu;               // low-half bits[2:16)
    unsigned i1 = ac >> 18;                          // high-half bits[2:16)
    unsigned r = (unsigned)lut[i0] | ((unsigned)lut[i1] << 16);
    r |= (yu & 0x80008000u);                         // apply sign -> +-0.5*tanh
    return __hadd2(*reinterpret_cast<__half2*>(&r), __float2half2_rn(0.5f));
}

// ---------------------------------------------------------------------------
// Gate-split fused LSTM (R9 body): 2-warp CTA owns 8 batch rows; warp p owns
// units [16p,16p+16), all 4 gates. R13: input & output gate sigmoids via a
// shared-memory LUT (bit-pattern indexed, log-spaced buckets) -> MUFU demand
// drops from 10 to 6 tanh2 per thread-step (forget gate + both tanh stay on
// MUFU for accuracy).
// ---------------------------------------------------------------------------
__global__ void __launch_bounds__(64, 13) lstm_fused(
    const float* __restrict__ x,
    const int* __restrict__ mat_idx, const int* __restrict__ freq_idx,
    const float* __restrict__ W_ih, const float* __restrict__ W_hh,
    const float* __restrict__ b_ih, const float* __restrict__ b_hh,
    const float* __restrict__ mat_emb, const float* __restrict__ freq_emb,
    const float* __restrict__ fc_w, const float* __restrict__ fc_b,
    float* __restrict__ out, int T)
{
    __shared__ unsigned long long sx[2][2][32];  // [buf][warp][lane] h-frags
    __shared__ float sred[2][4][2];              // fc partials
    __shared__ unsigned s_xh[32][16];            // [step][row*2+q] packed x
    __shared__ unsigned short slut[LUT_N];       // sigmoid LUT (0.5*tanh|x|)

    const int tid  = threadIdx.x;
    const int wid  = tid >> 5, lane = tid & 31;
    const int q    = lane & 3;            // batch col-pair selector
    const int gid  = lane >> 2;           // row-in-tile

    const long long rowbase = (long long)blockIdx.x * 8;

    // ---- fill sigmoid LUT (one-time; accurate tanhf) ----
    for (int j = tid; j < LUT_N; j += 64) {
        unsigned short bits = (unsigned short)((j << 2) | 2);
        __half hx = *reinterpret_cast<__half*>(&bits);
        float v = 0.5f * tanhf(__half2float(hx));
        __half hv = __float2half_rn(v);
        slut[j] = *reinterpret_cast<unsigned short*>(&hv);
    }

    // ---- stationary A fragments; 0.5 folded into sigmoid gates (i,f,o) ----
    auto wval = [&](int n, int k) -> float {
        float v;
        if (k < 32)       v = W_hh[n * 32 + k];
        else if (k < 35)  v = W_ih[n * 3 + (k - 32)];
        else if (k == 35) v = b_ih[n] + b_hh[n];
        else              v = 0.f;
        if ((n >> 5) != 2) v *= 0.5f;      // gates i,f,o scaled; g untouched
        return v;
    };
    unsigned af[4][2][4];   // gate, k16-chunk, frag
    unsigned af2[4][2];     // k8 chunk (x + bias)
#pragma unroll
    for (int g = 0; g < 4; ++g) {
        int n0 = g * 32 + 16 * wid + gid, n1 = n0 + 8;
#pragma unroll
        for (int kc = 0; kc < 2; ++kc) {
            int k0 = 16 * kc + 2 * q;
            af[g][kc][0] = pack2(wval(n0, k0),     wval(n0, k0 + 1));
            af[g][kc][1] = pack2(wval(n1, k0),     wval(n1, k0 + 1));
            af[g][kc][2] = pack2(wval(n0, k0 + 8), wval(n0, k0 + 9));
            af[g][kc][3] = pack2(wval(n1, k0 + 8), wval(n1, k0 + 9));
        }
        int k2 = 32 + 2 * q;
        af2[g][0] = pack2(wval(n0, k2), wval(n0, k2 + 1));
        af2[g][1] = pack2(wval(n1, k2), wval(n1, k2 + 1));
    }

    // ---- x staging setup: thread (xr=tid>>3, xseg=tid&7) handles 4 steps ----
    const int xr = tid >> 3, xseg = tid & 7;
    const float4* xsrc =
        reinterpret_cast<const float4*>(x + (size_t)(rowbase + xr) * T * 3)
        + xseg * 3;                        // 12 floats = steps 4*xseg..+4

    // ---- loop-carried state ----
    unsigned b00 = 0, b01 = 0, b10 = 0, b11 = 0;   // h fragments (t=0: 0)
    __half2 cst[2];
    cst[0] = __float2half2_rn(0.f);
    cst[1] = __float2half2_rn(0.f);
    unsigned hs[2];
    hs[0] = hs[1] = 0u;
    unsigned acc[4][2];                    // lives across the barrier

    const bool xlane = (q < 2);
    const unsigned* xrd = &s_xh[0][gid * 2 + q];  // step stride = 16 words

    for (int tc = 0; tc < T; tc += 32) {
        // ---- stage chunk: 3x LDG.128, pre-pack to half2, STS ----
        {
            const float4* src = xsrc + (tc >> 5) * 24;   // 96 floats/chunk/row
            float4 v0 = src[0], v1 = src[1], v2 = src[2];
            float f[12] = {v0.x, v0.y, v0.z, v0.w, v1.x, v1.y, v1.z, v1.w,
                           v2.x, v2.y, v2.z, v2.w};
#pragma unroll
            for (int k = 0; k < 4; ++k) {
                s_xh[xseg * 4 + k][xr * 2 + 0] = pack2(f[3 * k], f[3 * k + 1]);
                s_xh[xseg * 4 + k][xr * 2 + 1] = pack2(f[3 * k + 2], 1.0f);
            }
        }
        __syncthreads();

        // deferred x-projection for step tc (chunk-boundary step)
        {
            unsigned b2 = 0u;
            if (xlane) b2 = xrd[0];
#pragma unroll
            for (int g = 0; g < 4; ++g)
                mmaf16_1688(acc[g], af2[g], b2, 0u, 0u);
        }

#pragma unroll 4
        for (int tl = 0; tl < 32; ++tl) {
            const int buf = tl & 1;

            // ---- 8 h-MMAs chained onto acc (which holds xproj + bias) ----
#pragma unroll
            for (int g = 0; g < 4; ++g)
                mmaf16_16816(acc[g], af[g][0], b00, b01, acc[g][0], acc[g][1]);
#pragma unroll
            for (int g = 0; g < 4; ++g)
                mmaf16_16816(acc[g], af[g][1], b10, b11, acc[g][0], acc[g][1]);

            // ---- LSTM update: i,o via LUT (no MUFU); f,g,tanh(c) on MUFU ----
#pragma unroll
            for (int s = 0; s < 2; ++s) {
                __half2 si = sig_lut(acc[0][s], slut);
                __half2 sf = sig2h(u2h(acc[1][s]));
                __half2 tg = tanh2(u2h(acc[2][s]));
                __half2 so = sig_lut(acc[3][s], slut);
                __half2 cc = __hfma2(sf, cst[s], __hmul2(si, tg));
                cst[s] = cc;
                __half2 hv = __hmul2(so, tanh2(cc));
                hs[s] = *reinterpret_cast<unsigned*>(&hv);
            }

            // ---- own fragments in regs; partner half via SMEM ----
            unsigned f0 = movmt(hs[0]);    // k-rows 16*wid   .. +8
            unsigned f1 = movmt(hs[1]);    // k-rows 16*wid+8 .. +16
            sx[buf][wid][lane] =
                (unsigned long long)f0 | ((unsigned long long)f1 << 32);

            // ---- barrier shadow: x-projection MMAs for step t+1 ----
            if (tl < 31) {
                unsigned b2n = 0u;
                if (xlane) b2n = xrd[(tl + 1) * 16];
#pragma unroll
                for (int g = 0; g < 4; ++g)
                    mmaf16_1688(acc[g], af2[g], b2n, 0u, 0u);
            }

            __syncthreads();
            unsigned long long w = sx[buf][wid ^ 1][lane];
            if (wid == 0) {
                b00 = f0;          b01 = f1;
                b10 = (unsigned)w; b11 = (unsigned)(w >> 32);
            } else {
                b00 = (unsigned)w; b01 = (unsigned)(w >> 32);
                b10 = f0;          b11 = f1;
            }
        }
    }

    // ---- fc head: partial over this warp's 16 units, then pair-reduce ----
    float p_lo = 0.f, p_hi = 0.f;          // batch rows rowbase+2q, +2q+1
#pragma unroll
    for (int s = 0; s < 2; ++s) {
        __half2 hv = u2h(hs[s]);
        float w = fc_w[16 * wid + 8 * s + gid];
        p_lo = fmaf(__low2float(hv),  w, p_lo);
        p_hi = fmaf(__high2float(hv), w, p_hi);
    }
#pragma unroll
    for (int off = 4; off < 32; off <<= 1) {
        p_lo += __shfl_xor_sync(0xFFFFFFFFu, p_lo, off);
        p_hi += __shfl_xor_sync(0xFFFFFFFFu, p_hi, off);
    }
    if (lane < 4) { sred[wid][q][0] = p_lo; sred[wid][q][1] = p_hi; }
    __syncthreads();
    if (tid < 4) {
        float base = fc_b[0];
#pragma unroll
        for (int k = 0; k < 2; ++k) {
            long long r = rowbase + 2 * tid + k;
            float s = sred[0][tid][k] + sred[1][tid][k] + base;
            int mi = mat_idx[r], fi = freq_idx[r];
#pragma unroll
            for (int e = 0; e < 4; ++e) s += mat_emb[mi * 4 + e] * fc_w[32 + e];
#pragma unroll
            for (int e = 0; e < 2; ++e) s += freq_emb[fi * 2 + e] * fc_w[36 + e];
            out[r] = s;
        }
    }
}

extern "C" void kernel_launch(void* const* d_in, const int* in_sizes, int n_in,
                              void* d_out, int out_size) {
    const float* x        = (const float*)d_in[0];
    const int*   mat_idx  = (const int*)  d_in[1];
    const int*   freq_idx = (const int*)  d_in[2];
    const float* W_ih     = (const float*)d_in[3];
    const float* W_hh     = (const float*)d_in[4];
    const float* b_ih     = (const float*)d_in[5];
    const float* b_hh     = (const float*)d_in[6];
    const float* mat_emb  = (const float*)d_in[7];
    const float* freq_emb = (const float*)d_in[8];
    const float* fc_w     = (const float*)d_in[9];
    const float* fc_b     = (const float*)d_in[10];

    int B = in_sizes[1];                  // mat_idx has B elements
    int T = in_sizes[0] / (B * 3);        // x has B*T*3 elements
    int grid = B / 8;                     // 8 rows per 2-warp CTA

    lstm_fused<<<grid, 64>>>(x, mat_idx, freq_idx, W_ih, W_hh, b_ih, b_hh,
                             mat_emb, freq_emb, fc_w, fc_b,
                             (float*)d_out, T);
}

// round 14
// speedup vs baseline: 1.2660x; 1.0128x over previous
#include <cuda_runtime.h>
#include <cuda_fp16.h>
#include <math.h>

// ---------------------------------------------------------------------------
// f16-accumulate MMA + movmatrix wrappers (sm_75+/sm_80, fine on compute_103)
// ---------------------------------------------------------------------------
__device__ __forceinline__ void mmaf16_16816(unsigned* d, const unsigned* a,
                                             unsigned b0, unsigned b1,
                                             unsigned c0, unsigned c1) {
    asm volatile(
        "mma.sync.aligned.m16n8k16.row.col.f16.f16.f16.f16 "
        "{%0,%1}, {%2,%3,%4,%5}, {%6,%7}, {%8,%9};"
        : "=r"(d[0]), "=r"(d[1])
        : "r"(a[0]), "r"(a[1]), "r"(a[2]), "r"(a[3]),
          "r"(b0), "r"(b1), "r"(c0), "r"(c1));
}
__device__ __forceinline__ void mmaf16_1688(unsigned* d, const unsigned* a,
                                            unsigned b0,
                                            unsigned c0, unsigned c1) {
    asm volatile(
        "mma.sync.aligned.m16n8k8.row.col.f16.f16.f16.f16 "
        "{%0,%1}, {%2,%3}, {%4}, {%5,%6};"
        : "=r"(d[0]), "=r"(d[1])
        : "r"(a[0]), "r"(a[1]), "r"(b0), "r"(c0), "r"(c1));
}
__device__ __forceinline__ unsigned movmt(unsigned a) {
    unsigned d;
    asm("movmatrix.sync.aligned.m8n8.trans.b16 %0, %1;" : "=r"(d) : "r"(a));
    return d;
}
__device__ __forceinline__ __half2 tanh2(__half2 x) {
    unsigned xi = *reinterpret_cast<unsigned*>(&x), yi;
    asm("tanh.approx.f16x2 %0, %1;" : "=r"(yi) : "r"(xi));
    return *reinterpret_cast<__half2*>(&yi);
}
// sigmoid with the 0.5 pre-folded into the weights: sig(2y) = 0.5*tanh(y)+0.5
__device__ __forceinline__ __half2 sig2h(__half2 y) {
    const __half2 h05 = __float2half2_rn(0.5f);
    return __hfma2(tanh2(y), h05, h05);
}
__device__ __forceinline__ unsigned pack2(float lo, float hi) {
    __half2 h = __floats2half2_rn(lo, hi);
    return *reinterpret_cast<unsigned*>(&h);
}
__device__ __forceinline__ __half2 u2h(unsigned u) {
    return *reinterpret_cast<__half2*>(&u);
}

// ---- LUT sigmoid (no MUFU): sigma = 0.5 + sign(y) * lut[|y| bit-bucket] ----
// lut[j] = 0.5*tanh(value of f16 bits (j<<2)|2), j in [0, 4420).
static constexpr int LUT_N = 4420;
__device__ __forceinline__ __half2 sig_lut(unsigned yu,
                                           const unsigned short* lut) {
    unsigned au = yu & 0x7FFF7FFFu;                  // |y| per half
    __half2 a = *reinterpret_cast<__half2*>(&au);
    a = __hmin2(a, __float2half2_rn(4.99f));         // clamp below 5.0
    unsigned ac = *reinterpret_cast<unsigned*>(&a);
    unsigned i0 = (ac >> 2) & 0x3FFFu;               // low-half bits[2:16)
    unsigned i1 = ac >> 18;                          // high-half bits[2:16)
    unsigned r = (unsigned)lut[i0] | ((unsigned)lut[i1] << 16);
    r |= (yu & 0x80008000u);                         // apply sign -> +-0.5*tanh
    return __hadd2(*reinterpret_cast<__half2*>(&r), __float2half2_rn(0.5f));
}

// ---------------------------------------------------------------------------
// Gate-split fused LSTM: 2-warp CTA owns 8 batch rows; warp p owns units
// [16p,16p+16), all 4 gates. R14:
//  - activation rebalance: 3 sigmoids via LUT (6 LDS), sigma_o of slot 1 +
//    sigma_f + both tanh on MUFU (7 tanh2) -> L1 and MUFU walls equalized;
//  - x reads vectorized: slot-major padded layout, 1 LDS.128 per 4 steps;
//  - launch_bounds(64,14) to admit the full 27.7 warps/SM the grid supplies.
// ---------------------------------------------------------------------------
__global__ void __launch_bounds__(64, 14) lstm_fused(
    const float* __restrict__ x,
    const int* __restrict__ mat_idx, const int* __restrict__ freq_idx,
    const float* __restrict__ W_ih, const float* __restrict__ W_hh,
    const float* __restrict__ b_ih, const float* __restrict__ b_hh,
    const float* __restrict__ mat_emb, const float* __restrict__ freq_emb,
    const float* __restrict__ fc_w, const float* __restrict__ fc_b,
    float* __restrict__ out, int T)
{
    __shared__ unsigned long long sx[2][2][32];  // [buf][warp][lane] h-frags
    __shared__ float sred[2][4][2];              // fc partials
    __shared__ unsigned s_xh[16][36];            // [slot][step] packed x (pad)
    __shared__ unsigned short slut[LUT_N];       // sigmoid LUT (0.5*tanh|x|)

    const int tid  = threadIdx.x;
    const int wid  = tid >> 5, lane = tid & 31;
    const int q    = lane & 3;            // batch col-pair selector
    const int gid  = lane >> 2;           // row-in-tile

    const long long rowbase = (long long)blockIdx.x * 8;

    // ---- fill sigmoid LUT (one-time; accurate tanhf) ----
    for (int j = tid; j < LUT_N; j += 64) {
        unsigned short bits = (unsigned short)((j << 2) | 2);
        __half hx = *reinterpret_cast<__half*>(&bits);
        float v = 0.5f * tanhf(__half2float(hx));
        __half hv = __float2half_rn(v);
        slut[j] = *reinterpret_cast<unsigned short*>(&hv);
    }

    // ---- stationary A fragments; 0.5 folded into sigmoid gates (i,f,o) ----
    auto wval = [&](int n, int k) -> float {
        float v;
        if (k < 32)       v = W_hh[n * 32 + k];
        else if (k < 35)  v = W_ih[n * 3 + (k - 32)];
        else if (k == 35) v = b_ih[n] + b_hh[n];
        else              v = 0.f;
        if ((n >> 5) != 2) v *= 0.5f;      // gates i,f,o scaled; g untouched
        return v;
    };
    unsigned af[4][2][4];   // gate, k16-chunk, frag
    unsigned af2[4][2];     // k8 chunk (x + bias)
#pragma unroll
    for (int g = 0; g < 4; ++g) {
        int n0 = g * 32 + 16 * wid + gid, n1 = n0 + 8;
#pragma unroll
        for (int kc = 0; kc < 2; ++kc) {
            int k0 = 16 * kc + 2 * q;
            af[g][kc][0] = pack2(wval(n0, k0),     wval(n0, k0 + 1));
            af[g][kc][1] = pack2(wval(n1, k0),     wval(n1, k0 + 1));
            af[g][kc][2] = pack2(wval(n0, k0 + 8), wval(n0, k0 + 9));
            af[g][kc][3] = pack2(wval(n1, k0 + 8), wval(n1, k0 + 9));
        }
        int k2 = 32 + 2 * q;
        af2[g][0] = pack2(wval(n0, k2), wval(n0, k2 + 1));
        af2[g][1] = pack2(wval(n1, k2), wval(n1, k2 + 1));
    }

    // ---- x staging setup: thread (xr=tid>>3, xseg=tid&7) handles 4 steps ----
    const int xr = tid >> 3, xseg = tid & 7;
    const float4* xsrc =
        reinterpret_cast<const float4*>(x + (size_t)(rowbase + xr) * T * 3)
        + xseg * 3;                        // 12 floats = steps 4*xseg..+4

    // ---- loop-carried state ----
    unsigned b00 = 0, b01 = 0, b10 = 0, b11 = 0;   // h fragments (t=0: 0)
    __half2 cst[2];
    cst[0] = __float2half2_rn(0.f);
    cst[1] = __float2half2_rn(0.f);
    unsigned hs[2];
    hs[0] = hs[1] = 0u;

    const bool xlane = (q < 2);
    const unsigned* xrd = &s_xh[gid * 2 + q][0];   // this lane's slot row

    for (int tc = 0; tc < T; tc += 32) {
        // ---- stage chunk: 3x LDG.128, pre-pack to half2, STS ----
        {
            const float4* src = xsrc + (tc >> 5) * 24;   // 96 floats/chunk/row
            float4 v0 = src[0], v1 = src[1], v2 = src[2];
            float f[12] = {v0.x, v0.y, v0.z, v0.w, v1.x, v1.y, v1.z, v1.w,
                           v2.x, v2.y, v2.z, v2.w};
#pragma unroll
            for (int k = 0; k < 4; ++k) {
                s_xh[xr * 2 + 0][xseg * 4 + k] = pack2(f[3 * k], f[3 * k + 1]);
                s_xh[xr * 2 + 1][xseg * 4 + k] = pack2(f[3 * k + 2], 1.0f);
            }
        }
        __syncthreads();

        for (int t4 = 0; t4 < 32; t4 += 4) {
            // x for 4 steps: one LDS.128 (aligned: slot stride 36 words)
            uint4 xv = make_uint4(0u, 0u, 0u, 0u);
            if (xlane) xv = *reinterpret_cast<const uint4*>(xrd + t4);

#pragma unroll
            for (int k = 0; k < 4; ++k) {
                const int tl = t4 + k;
                const int buf = tl & 1;
                const unsigned b2 = (k == 0) ? xv.x : (k == 1) ? xv.y
                                  : (k == 2) ? xv.z : xv.w;

                // ---- 12 MMAs: xproj + bias, then the two h chunks ----
                unsigned acc[4][2];
#pragma unroll
                for (int g = 0; g < 4; ++g)
                    mmaf16_1688(acc[g], af2[g], b2, 0u, 0u);
#pragma unroll
                for (int g = 0; g < 4; ++g)
                    mmaf16_16816(acc[g], af[g][0], b00, b01,
                                 acc[g][0], acc[g][1]);
#pragma unroll
                for (int g = 0; g < 4; ++g)
                    mmaf16_16816(acc[g], af[g][1], b10, b11,
                                 acc[g][0], acc[g][1]);

                // ---- LSTM update: LUT for sig_i (both slots) + sig_o
                //      slot 0; MUFU for sig_f, tanh(g), tanh(c), sig_o s1 ----
                {
                    __half2 si = sig_lut(acc[0][0], slut);
                    __half2 so = sig_lut(acc[3][0], slut);
                    __half2 sf = sig2h(u2h(acc[1][0]));
                    __half2 tg = tanh2(u2h(acc[2][0]));
                    __half2 cc = __hfma2(sf, cst[0], __hmul2(si, tg));
                    cst[0] = cc;
                    __half2 hv = __hmul2(so, tanh2(cc));
                    hs[0] = *reinterpret_cast<unsigned*>(&hv);
                }
                {
                    __half2 si = sig_lut(acc[0][1], slut);
                    __half2 sf = sig2h(u2h(acc[1][1]));
                    __half2 tg = tanh2(u2h(acc[2][1]));
                    __half2 so = sig2h(u2h(acc[3][1]));
                    __half2 cc = __hfma2(sf, cst[1], __hmul2(si, tg));
                    cst[1] = cc;
                    __half2 hv = __hmul2(so, tanh2(cc));
                    hs[1] = *reinterpret_cast<unsigned*>(&hv);
                }

                // ---- own fragments in regs; partner half via SMEM ----
                unsigned f0 = movmt(hs[0]);    // k-rows 16*wid   .. +8
                unsigned f1 = movmt(hs[1]);    // k-rows 16*wid+8 .. +16
                sx[buf][wid][lane] =
                    (unsigned long long)f0 | ((unsigned long long)f1 << 32);
                __syncthreads();
                unsigned long long w = sx[buf][wid ^ 1][lane];
                if (wid == 0) {
                    b00 = f0;          b01 = f1;
                    b10 = (unsigned)w; b11 = (unsigned)(w >> 32);
                } else {
                    b00 = (unsigned)w; b01 = (unsigned)(w >> 32);
                    b10 = f0;          b11 = f1;
                }
            }
        }
    }

    // ---- fc head: partial over this warp's 16 units, then pair-reduce ----
    float p_lo = 0.f, p_hi = 0.f;          // batch rows rowbase+2q, +2q+1
#pragma unroll
    for (int s = 0; s < 2; ++s) {
        __half2 hv = u2h(hs[s]);
        float w = fc_w[16 * wid + 8 * s + gid];
        p_lo = fmaf(__low2float(hv),  w, p_lo);
        p_hi = fmaf(__high2float(hv), w, p_hi);
    }
#pragma unroll
    for (int off = 4; off < 32; off <<= 1) {
        p_lo += __shfl_xor_sync(0xFFFFFFFFu, p_lo, off);
        p_hi += __shfl_xor_sync(0xFFFFFFFFu, p_hi, off);
    }
    if (lane < 4) { sred[wid][q][0] = p_lo; sred[wid][q][1] = p_hi; }
    __syncthreads();
    if (tid < 4) {
        float base = fc_b[0];
#pragma unroll
        for (int k = 0; k < 2; ++k) {
            long long r = rowbase + 2 * tid + k;
            float s = sred[0][tid][k] + sred[1][tid][k] + base;
            int mi = mat_idx[r], fi = freq_idx[r];
#pragma unroll
            for (int e = 0; e < 4; ++e) s += mat_emb[mi * 4 + e] * fc_w[32 + e];
#pragma unroll
            for (int e = 0; e < 2; ++e) s += freq_emb[fi * 2 + e] * fc_w[36 + e];
            out[r] = s;
        }
    }
}

extern "C" void kernel_launch(void* const* d_in, const int* in_sizes, int n_in,
                              void* d_out, int out_size) {
    const float* x        = (const float*)d_in[0];
    const int*   mat_idx  = (const int*)  d_in[1];
    const int*   freq_idx = (const int*)  d_in[2];
    const float* W_ih     = (const float*)d_in[3];
    const float* W_hh     = (const float*)d_in[4];
    const float* b_ih     = (const float*)d_in[5];
    const float* b_hh     = (const float*)d_in[6];
    const float* mat_emb  = (const float*)d_in[7];
    const float* freq_emb = (const float*)d_in[8];
    const float* fc_w     = (const float*)d_in[9];
    const float* fc_b     = (const float*)d_in[10];

    int B = in_sizes[1];                  // mat_idx has B elements
    int T = in_sizes[0] / (B * 3);        // x has B*T*3 elements
    int grid = B / 8;                     // 8 rows per 2-warp CTA

    lstm_fused<<<grid, 64>>>(x, mat_idx, freq_idx, W_ih, W_hh, b_ih, b_hh,
                             mat_emb, freq_emb, fc_w, fc_b,
                             (float*)d_out, T);
}

// round 15
// speedup vs baseline: 1.3742x; 1.0854x over previous
#include <cuda_runtime.h>
#include <cuda_fp16.h>
#include <math.h>

// ---------------------------------------------------------------------------
// f16-accumulate MMA + movmatrix wrappers (sm_75+/sm_80, fine on compute_103)
// ---------------------------------------------------------------------------
__device__ __forceinline__ void mmaf16_16816(unsigned* d, const unsigned* a,
                                             unsigned b0, unsigned b1,
                                             unsigned c0, unsigned c1) {
    asm volatile(
        "mma.sync.aligned.m16n8k16.row.col.f16.f16.f16.f16 "
        "{%0,%1}, {%2,%3,%4,%5}, {%6,%7}, {%8,%9};"
        : "=r"(d[0]), "=r"(d[1])
        : "r"(a[0]), "r"(a[1]), "r"(a[2]), "r"(a[3]),
          "r"(b0), "r"(b1), "r"(c0), "r"(c1));
}
__device__ __forceinline__ void mmaf16_1688(unsigned* d, const unsigned* a,
                                            unsigned b0,
                                            unsigned c0, unsigned c1) {
    asm volatile(
        "mma.sync.aligned.m16n8k8.row.col.f16.f16.f16.f16 "
        "{%0,%1}, {%2,%3}, {%4}, {%5,%6};"
        : "=r"(d[0]), "=r"(d[1])
        : "r"(a[0]), "r"(a[1]), "r"(b0), "r"(c0), "r"(c1));
}
__device__ __forceinline__ unsigned movmt(unsigned a) {
    unsigned d;
    asm("movmatrix.sync.aligned.m8n8.trans.b16 %0, %1;" : "=r"(d) : "r"(a));
    return d;
}
__device__ __forceinline__ __half2 tanh2(__half2 x) {
    unsigned xi = *reinterpret_cast<unsigned*>(&x), yi;
    asm("tanh.approx.f16x2 %0, %1;" : "=r"(yi) : "r"(xi));
    return *reinterpret_cast<__half2*>(&yi);
}
// sigmoid with the 0.5 pre-folded into the weights: sig(2y) = 0.5*tanh(y)+0.5
__device__ __forceinline__ __half2 sig2h(__half2 y) {
    const __half2 h05 = __float2half2_rn(0.5f);
    return __hfma2(tanh2(y), h05, h05);
}
__device__ __forceinline__ unsigned pack2(float lo, float hi) {
    __half2 h = __floats2half2_rn(lo, hi);
    return *reinterpret_cast<unsigned*>(&h);
}
__device__ __forceinline__ __half2 u2h(unsigned u) {
    return *reinterpret_cast<__half2*>(&u);
}
__device__ __forceinline__ unsigned smem_u32x(const void* p) {
    unsigned a;
    asm("{ .reg .u64 t; cvta.to.shared.u64 t, %1; cvt.u32.u64 %0, t; }"
        : "=r"(a) : "l"(p));
    return a;
}

#define MBAR_INIT(addr, cnt) \
    asm volatile("mbarrier.init.shared.b64 [%0], %1;" \
                 :: "r"(addr), "r"(cnt) : "memory")
#define MBAR_ARRIVE(addr) \
    asm volatile("mbarrier.arrive.shared.b64 _, [%0];" \
                 :: "r"(addr) : "memory")
__device__ __forceinline__ void mbar_wait(unsigned addr, unsigned parity) {
    asm volatile(
        "{\n\t"
        ".reg .pred P1;\n\t"
        "WL_%=:\n\t"
        "mbarrier.try_wait.parity.acquire.cta.shared::cta.b64 P1, [%0], %1, 0x989680;\n\t"
        "@P1 bra.uni WD_%=;\n\t"
        "bra.uni WL_%=;\n\t"
        "WD_%=:\n\t"
        "}"
        :: "r"(addr), "r"(parity) : "memory");
}

// ---- LUT sigmoid (no MUFU): sigma = 0.5 + sign(y) * lut[|y| bit-bucket] ----
static constexpr int LUT_N = 4420;
__device__ __forceinline__ __half2 sig_lut(unsigned yu,
                                           const unsigned short* lut) {
    unsigned au = yu & 0x7FFF7FFFu;                  // |y| per half
    __half2 a = *reinterpret_cast<__half2*>(&au);
    a = __hmin2(a, __float2half2_rn(4.99f));         // clamp below 5.0
    unsigned ac = *reinterpret_cast<unsigned*>(&a);
    unsigned i0 = (ac >> 2) & 0x3FFFu;               // low-half bits[2:16)
    unsigned i1 = ac >> 18;                          // high-half bits[2:16)
    unsigned r = (unsigned)lut[i0] | ((unsigned)lut[i1] << 16);
    r |= (yu & 0x80008000u);                         // apply sign -> +-0.5*tanh
    return __hadd2(*reinterpret_cast<__half2*>(&r), __float2half2_rn(0.5f));
}

// ---------------------------------------------------------------------------
// Gate-split fused LSTM. R15: mbarrier split-barrier pipeline —
//   epilogue -> movmt -> STS -> mbarrier.ARRIVE -> [next step: 4 k8 x-proj
//   MMAs + 4 OWN-half k16 MMAs] -> mbarrier.WAIT -> LDS partner -> 4 partner
//   MMAs -> epilogue.  8 of 12 MMAs execute inside the barrier-skew window.
// Weight chunks are per-warp permuted (chunk0 = own k-cols) so the exchange
// is branchless (R12 scheme). Activation mix (3 LUT / 7 MUFU) per R14.
// ---------------------------------------------------------------------------
__global__ void __launch_bounds__(64, 14) lstm_fused(
    const float* __restrict__ x,
    const int* __restrict__ mat_idx, const int* __restrict__ freq_idx,
    const float* __restrict__ W_ih, const float* __restrict__ W_hh,
    const float* __restrict__ b_ih, const float* __restrict__ b_hh,
    const float* __restrict__ mat_emb, const float* __restrict__ freq_emb,
    const float* __restrict__ fc_w, const float* __restrict__ fc_b,
    float* __restrict__ out, int T)
{
    __shared__ unsigned long long sx[2][2][32];  // [slot][warp][lane] h-frags
    __shared__ float sred[2][4][2];              // fc partials
    __shared__ unsigned s_xh[16][36];            // [slot][step] packed x (pad)
    __shared__ unsigned short slut[LUT_N];       // sigmoid LUT (0.5*tanh|x|)
    __shared__ __align__(8) unsigned long long mbar[2];

    const int tid  = threadIdx.x;
    const int wid  = tid >> 5, lane = tid & 31;
    const int q    = lane & 3;            // batch col-pair selector
    const int gid  = lane >> 2;           // row-in-tile

    const long long rowbase = (long long)blockIdx.x * 8;
    const unsigned mb0 = smem_u32x(&mbar[0]);

    // ---- fill sigmoid LUT (one-time; accurate tanhf) ----
    for (int j = tid; j < LUT_N; j += 64) {
        unsigned short bits = (unsigned short)((j << 2) | 2);
        __half hx = *reinterpret_cast<__half*>(&bits);
        float v = 0.5f * tanhf(__half2float(hx));
        __half hv = __float2half_rn(v);
        slut[j] = *reinterpret_cast<unsigned short*>(&hv);
    }
    if (tid == 0) { MBAR_INIT(mb0, 64); MBAR_INIT(mb0 + 8, 64); }
    sx[1][wid][lane] = 0ull;               // t=0 reads zeros from slot 1

    // ---- stationary A fragments; 0.5 folded into sigmoid gates (i,f,o);
    //      chunk0 = OWN k-cols [16*wid,+16), chunk1 = partner's ----
    auto wval = [&](int n, int k) -> float {
        float v;
        if (k < 32)       v = W_hh[n * 32 + k];
        else if (k < 35)  v = W_ih[n * 3 + (k - 32)];
        else if (k == 35) v = b_ih[n] + b_hh[n];
        else              v = 0.f;
        if ((n >> 5) != 2) v *= 0.5f;      // gates i,f,o scaled; g untouched
        return v;
    };
    unsigned af[4][2][4];   // gate, chunk(own/partner), frag
    unsigned af2[4][2];     // k8 chunk (x + bias)
#pragma unroll
    for (int g = 0; g < 4; ++g) {
        int n0 = g * 32 + 16 * wid + gid, n1 = n0 + 8;
#pragma unroll
        for (int kc = 0; kc < 2; ++kc) {
            int k0 = 16 * ((kc == 0) ? wid : (1 - wid)) + 2 * q;
            af[g][kc][0] = pack2(wval(n0, k0),     wval(n0, k0 + 1));
            af[g][kc][1] = pack2(wval(n1, k0),     wval(n1, k0 + 1));
            af[g][kc][2] = pack2(wval(n0, k0 + 8), wval(n0, k0 + 9));
            af[g][kc][3] = pack2(wval(n1, k0 + 8), wval(n1, k0 + 9));
        }
        int k2 = 32 + 2 * q;
        af2[g][0] = pack2(wval(n0, k2), wval(n0, k2 + 1));
        af2[g][1] = pack2(wval(n1, k2), wval(n1, k2 + 1));
    }

    // ---- x staging setup: thread (xr=tid>>3, xseg=tid&7) handles 4 steps ----
    const int xr = tid >> 3, xseg = tid & 7;
    const float4* xsrc =
        reinterpret_cast<const float4*>(x + (size_t)(rowbase + xr) * T * 3)
        + xseg * 3;                        // 12 floats = steps 4*xseg..+4

    // ---- loop-carried state ----
    __half2 cst[2];
    cst[0] = __float2half2_rn(0.f);
    cst[1] = __float2half2_rn(0.f);
    unsigned hs[2];
    hs[0] = hs[1] = 0u;
    unsigned f0 = 0u, f1 = 0u;             // own h fragments (t=0: zero)

    __syncthreads();                       // mbar init + sx zero visible
    MBAR_ARRIVE(mb0 + 8);                  // prime slot-1 phase 0

    const bool xlane = (q < 2);
    const unsigned* xrd = &s_xh[gid * 2 + q][0];   // this lane's slot row

    for (int tc = 0; tc < T; tc += 32) {
        // ---- stage chunk: 3x LDG.128, pre-pack to half2, STS ----
        {
            const float4* src = xsrc + (tc >> 5) * 24;   // 96 floats/chunk/row
            float4 v0 = src[0], v1 = src[1], v2 = src[2];
            float f[12] = {v0.x, v0.y, v0.z, v0.w, v1.x, v1.y, v1.z, v1.w,
                           v2.x, v2.y, v2.z, v2.w};
#pragma unroll
            for (int k = 0; k < 4; ++k) {
                s_xh[xr * 2 + 0][xseg * 4 + k] = pack2(f[3 * k], f[3 * k + 1]);
                s_xh[xr * 2 + 1][xseg * 4 + k] = pack2(f[3 * k + 2], 1.0f);
            }
        }
        __syncthreads();

        for (int t4 = 0; t4 < 32; t4 += 4) {
            // x for 4 steps: one LDS.128 (slot stride 36 words)
            uint4 xv = make_uint4(0u, 0u, 0u, 0u);
            if (xlane) xv = *reinterpret_cast<const uint4*>(xrd + t4);

#pragma unroll
            for (int k = 0; k < 4; ++k) {
                const int tl = t4 + k;
                const int pub = tl & 1;                 // publish slot
                const unsigned par = (unsigned)((tl >> 1) & 1);  // wait parity
                const unsigned b2 = (k == 0) ? xv.x : (k == 1) ? xv.y
                                  : (k == 2) ? xv.z : xv.w;

                // ---- pre-wait: x-projection + OWN-half MMAs ----
                unsigned acc[4][2];
#pragma unroll
                for (int g = 0; g < 4; ++g)
                    mmaf16_1688(acc[g], af2[g], b2, 0u, 0u);
#pragma unroll
                for (int g = 0; g < 4; ++g)
                    mmaf16_16816(acc[g], af[g][0], f0, f1,
                                 acc[g][0], acc[g][1]);

                // ---- wait for partner's h(t-1) publish ----
                mbar_wait(mb0 + 8 * (1 - pub), par);
                const unsigned long long w = sx[1 - pub][wid ^ 1][lane];
#pragma unroll
                for (int g = 0; g < 4; ++g)
                    mmaf16_16816(acc[g], af[g][1],
                                 (unsigned)w, (unsigned)(w >> 32),
                                 acc[g][0], acc[g][1]);

                // ---- LSTM update (3 LUT sigmoids, 7 MUFU tanh2) ----
                {
                    __half2 si = sig_lut(acc[0][0], slut);
                    __half2 so = sig_lut(acc[3][0], slut);
                    __half2 sf = sig2h(u2h(acc[1][0]));
                    __half2 tg = tanh2(u2h(acc[2][0]));
                    __half2 cc = __hfma2(sf, cst[0], __hmul2(si, tg));
                    cst[0] = cc;
                    __half2 hv = __hmul2(so, tanh2(cc));
                    hs[0] = *reinterpret_cast<unsigned*>(&hv);
                }
                {
                    __half2 si = sig_lut(acc[0][1], slut);
                    __half2 sf = sig2h(u2h(acc[1][1]));
                    __half2 tg = tanh2(u2h(acc[2][1]));
                    __half2 so = sig2h(u2h(acc[3][1]));
                    __half2 cc = __hfma2(sf, cst[1], __hmul2(si, tg));
                    cst[1] = cc;
                    __half2 hv = __hmul2(so, tanh2(cc));
                    hs[1] = *reinterpret_cast<unsigned*>(&hv);
                }

                // ---- publish own fragments, arrive (non-blocking) ----
                f0 = movmt(hs[0]);     // own k-rows [16*wid, 16*wid+8)
                f1 = movmt(hs[1]);     // own k-rows [16*wid+8, 16*wid+16)
                sx[pub][wid][lane] =
                    (unsigned long long)f0 | ((unsigned long long)f1 << 32);
                MBAR_ARRIVE(mb0 + 8 * pub);
            }
        }
    }

    // ---- fc head: partial over this warp's 16 units, then pair-reduce ----
    float p_lo = 0.f, p_hi = 0.f;          // batch rows rowbase+2q, +2q+1
#pragma unroll
    for (int s = 0; s < 2; ++s) {
        __half2 hv = u2h(hs[s]);
        float w = fc_w[16 * wid + 8 * s + gid];
        p_lo = fmaf(__low2float(hv),  w, p_lo);
        p_hi = fmaf(__high2float(hv), w, p_hi);
    }
#pragma unroll
    for (int off = 4; off < 32; off <<= 1) {
        p_lo += __shfl_xor_sync(0xFFFFFFFFu, p_lo, off);
        p_hi += __shfl_xor_sync(0xFFFFFFFFu, p_hi, off);
    }
    if (lane < 4) { sred[wid][q][0] = p_lo; sred[wid][q][1] = p_hi; }
    __syncthreads();
    if (tid < 4) {
        float base = fc_b[0];
#pragma unroll
        for (int k = 0; k < 2; ++k) {
            long long r = rowbase + 2 * tid + k;
            float s = sred[0][tid][k] + sred[1][tid][k] + base;
            int mi = mat_idx[r], fi = freq_idx[r];
#pragma unroll
            for (int e = 0; e < 4; ++e) s += mat_emb[mi * 4 + e] * fc_w[32 + e];
#pragma unroll
            for (int e = 0; e < 2; ++e) s += freq_emb[fi * 2 + e] * fc_w[36 + e];
            out[r] = s;
        }
    }
}

extern "C" void kernel_launch(void* const* d_in, const int* in_sizes, int n_in,
                              void* d_out, int out_size) {
    const float* x        = (const float*)d_in[0];
    const int*   mat_idx  = (const int*)  d_in[1];
    const int*   freq_idx = (const int*)  d_in[2];
    const float* W_ih     = (const float*)d_in[3];
    const float* W_hh     = (const float*)d_in[4];
    const float* b_ih     = (const float*)d_in[5];
    const float* b_hh     = (const float*)d_in[6];
    const float* mat_emb  = (const float*)d_in[7];
    const float* freq_emb = (const float*)d_in[8];
    const float* fc_w     = (const float*)d_in[9];
    const float* fc_b     = (const float*)d_in[10];

    int B = in_sizes[1];                  // mat_idx has B elements
    int T = in_sizes[0] / (B * 3);        // x has B*T*3 elements
    int grid = B / 8;                     // 8 rows per 2-warp CTA

    lstm_fused<<<grid, 64>>>(x, mat_idx, freq_idx, W_ih, W_hh, b_ih, b_hh,
                             mat_emb, freq_emb, fc_w, fc_b,
                             (float*)d_out, T);
}